// round 7
// baseline (speedup 1.0000x reference)
#include <cuda_runtime.h>
#include <cuda_fp16.h>
#include <math.h>

// Problem constants (fixed by the dataset)
#define Cn   128          // channels
#define Hh   5            // heads
#define HC   (Hh*Cn)      // 640
#define MAXN 20000
#define MAXE 320000
#define MAXET (MAXE + MAXN)
#define EPSV 1e-16f
#define NEG_SLOPE 0.2f

// ---------------- scratch (static device globals; no runtime alloc) ----------
__device__ __align__(16) __half g_h[(size_t)MAXN * HC];  // [N,H,C] fp16 (25.6 MB)
__device__ float g_asrc[MAXN * Hh];
__device__ float g_adst[MAXN * Hh];
__device__ float g_denom[MAXN * Hh];
__device__ float g_rdenom[MAXN * Hh];
__device__ float g_w[(size_t)Hh * MAXET];                // planar [H][E'] exp values

// ---------------- kernel 0: init out = features + bias; zero denom ----------
__global__ void init_kernel(const float* __restrict__ features,
                            const float* __restrict__ bias,
                            float* __restrict__ out, int Nn) {
    int i = blockIdx.x * blockDim.x + threadIdx.x;
    int NC = Nn * Cn;
    if (i < NC) out[i] = features[i] + bias[i & (Cn - 1)];
    if (i < Nn * Hh) g_denom[i] = 0.0f;
}

// ---------------- tf32 tensor-core GEMM + fused logits -----------------------
#define TBM  128
#define TBK  32
#define APAD 36
#define BPAD 132
#define CH2S 69

__device__ __forceinline__ float tf32r(float x) {
    unsigned r;
    asm("cvt.rna.tf32.f32 %0, %1;" : "=r"(r) : "f"(x));
    return __uint_as_float(r);
}

__device__ __forceinline__ void mma_tf32(float d[4], const unsigned a[4],
                                         const unsigned b[2]) {
    asm volatile(
        "mma.sync.aligned.m16n8k8.row.col.f32.tf32.tf32.f32 "
        "{%0,%1,%2,%3}, {%4,%5,%6,%7}, {%8,%9}, {%0,%1,%2,%3};"
        : "+f"(d[0]), "+f"(d[1]), "+f"(d[2]), "+f"(d[3])
        : "r"(a[0]), "r"(a[1]), "r"(a[2]), "r"(a[3]), "r"(b[0]), "r"(b[1]));
}

__global__ __launch_bounds__(256, 2)
void gemm_tc_kernel(const float* __restrict__ A,
                    const float* __restrict__ B,
                    const float* __restrict__ att_src,
                    const float* __restrict__ att_dst,
                    int M) {
    __shared__ __align__(16) char smem_raw[35328];
    float*    As = (float*)smem_raw;               // [128][36]
    float*    Bs = (float*)(smem_raw + 18432);     // [32][132]
    unsigned* Cs = (unsigned*)smem_raw;            // [128][69] half2 pairs

    const int tid    = threadIdx.x;
    const int head   = blockIdx.x;
    const int rowBlk = blockIdx.y * TBM;
    const int lane   = tid & 31;
    const int wid    = tid >> 5;
    const int warpM  = wid & 1;
    const int warpN  = wid >> 1;
    const int gid    = lane >> 2;
    const int tig    = lane & 3;

    float acc[4][4][4];
    #pragma unroll
    for (int m = 0; m < 4; m++)
        #pragma unroll
        for (int n = 0; n < 4; n++)
            #pragma unroll
            for (int r = 0; r < 4; r++) acc[m][n][r] = 0.0f;

    const int aRow   = tid >> 1;
    const int aCbase = (tid & 1) * 16;
    const int bKrow  = tid >> 3;
    const int bF4    = tid & 7;
    const int gARow  = rowBlk + aRow;

    for (int kc = 0; kc < Cn; kc += TBK) {
        #pragma unroll
        for (int j = 0; j < 4; j++) {
            float4 v = make_float4(0.f, 0.f, 0.f, 0.f);
            if (gARow < M)
                v = *(const float4*)(A + (size_t)gARow * Cn + kc + aCbase + 4 * j);
            v.x = tf32r(v.x); v.y = tf32r(v.y); v.z = tf32r(v.z); v.w = tf32r(v.w);
            *(float4*)(As + aRow * APAD + aCbase + 4 * j) = v;
        }
        #pragma unroll
        for (int j = 0; j < 4; j++) {
            int col = (bF4 + 8 * j) * 4;
            float4 v = *(const float4*)(B + (size_t)(kc + bKrow) * HC + head * Cn + col);
            v.x = tf32r(v.x); v.y = tf32r(v.y); v.z = tf32r(v.z); v.w = tf32r(v.w);
            *(float4*)(Bs + bKrow * BPAD + col) = v;
        }
        __syncthreads();

        #pragma unroll
        for (int kk = 0; kk < 4; kk++) {
            const int kb = kk * 8;
            unsigned a[4][4], b[4][2];
            #pragma unroll
            for (int m = 0; m < 4; m++) {
                int r0 = warpM * 64 + m * 16 + gid;
                a[m][0] = __float_as_uint(As[r0 * APAD + kb + tig]);
                a[m][1] = __float_as_uint(As[(r0 + 8) * APAD + kb + tig]);
                a[m][2] = __float_as_uint(As[r0 * APAD + kb + tig + 4]);
                a[m][3] = __float_as_uint(As[(r0 + 8) * APAD + kb + tig + 4]);
            }
            #pragma unroll
            for (int n = 0; n < 4; n++) {
                int cb = warpN * 32 + n * 8 + gid;
                b[n][0] = __float_as_uint(Bs[(kb + tig) * BPAD + cb]);
                b[n][1] = __float_as_uint(Bs[(kb + tig + 4) * BPAD + cb]);
            }
            #pragma unroll
            for (int m = 0; m < 4; m++)
                #pragma unroll
                for (int n = 0; n < 4; n++)
                    mma_tf32(acc[m][n], a[m], b[n]);
        }
        __syncthreads();
    }

    #pragma unroll
    for (int m = 0; m < 4; m++) {
        int r0 = warpM * 64 + m * 16 + gid;
        #pragma unroll
        for (int n = 0; n < 4; n++) {
            int ch = warpN * 16 + n * 4 + tig;
            __half2 h01 = __floats2half2_rn(acc[m][n][0], acc[m][n][1]);
            __half2 h23 = __floats2half2_rn(acc[m][n][2], acc[m][n][3]);
            Cs[r0 * CH2S + ch]       = *(unsigned*)&h01;
            Cs[(r0 + 8) * CH2S + ch] = *(unsigned*)&h23;
        }
    }
    __syncthreads();

    if (tid < TBM) {
        int gRow = rowBlk + tid;
        if (gRow < M) {
            const float* asv = att_src + head * Cn;
            const float* adv = att_dst + head * Cn;
            float ps = 0.f, pd = 0.f;
            #pragma unroll 8
            for (int i = 0; i < 64; i++) {
                unsigned u = Cs[tid * CH2S + i];
                float2 f = __half22float2(*(__half2*)&u);
                ps = fmaf(f.x, __ldg(asv + 2 * i), ps);
                ps = fmaf(f.y, __ldg(asv + 2 * i + 1), ps);
                pd = fmaf(f.x, __ldg(adv + 2 * i), pd);
                pd = fmaf(f.y, __ldg(adv + 2 * i + 1), pd);
            }
            g_asrc[gRow * Hh + head] = ps;
            g_adst[gRow * Hh + head] = pd;
        }
    }

    unsigned* gh = (unsigned*)g_h;
    #pragma unroll
    for (int i = 0; i < 32; i++) {
        int idx  = i * 256 + tid;
        int row  = idx >> 6;
        int ch   = idx & 63;
        int gRow = rowBlk + row;
        if (gRow < M)
            gh[(size_t)gRow * (HC / 2) + head * 64 + ch] = Cs[row * CH2S + ch];
    }
}

// ---------------- kernel 2: exp + segment sum; stash exp in g_w --------------
__global__ void denom_kernel(const int* __restrict__ ei, int E, int Etot) {
    int e = blockIdx.x * blockDim.x + threadIdx.x;
    if (e >= Etot) return;
    int src, dst;
    if (e < E) { src = ei[e]; dst = ei[E + e]; }
    else       { src = e - E; dst = src; }
    #pragma unroll
    for (int h = 0; h < Hh; h++) {
        float v = g_asrc[src * Hh + h] + g_adst[dst * Hh + h];
        v = v > 0.f ? v : NEG_SLOPE * v;
        float t = __expf(v);
        g_w[(size_t)h * Etot + e] = t;        // planar: coalesced write
        atomicAdd(&g_denom[dst * Hh + h], t);
    }
}

// ---------------- kernel 2.5: reciprocal denominators (fold 1/H) -------------
__global__ void rdenom_kernel(int n) {
    int i = blockIdx.x * blockDim.x + threadIdx.x;
    if (i < n) g_rdenom[i] = (1.0f / Hh) / (g_denom[i] + EPSV);
}

// ---------------- helper: accumulate 8 fp16 channels of one head -------------
__device__ __forceinline__ void acc_head8(float* a, uint4 u, float w) {
    float2 f0 = __half22float2(*(const __half2*)&u.x);
    float2 f1 = __half22float2(*(const __half2*)&u.y);
    float2 f2 = __half22float2(*(const __half2*)&u.z);
    float2 f3 = __half22float2(*(const __half2*)&u.w);
    a[0] = fmaf(w, f0.x, a[0]); a[1] = fmaf(w, f0.y, a[1]);
    a[2] = fmaf(w, f1.x, a[2]); a[3] = fmaf(w, f1.y, a[3]);
    a[4] = fmaf(w, f2.x, a[4]); a[5] = fmaf(w, f2.y, a[5]);
    a[6] = fmaf(w, f3.x, a[6]); a[7] = fmaf(w, f3.y, a[7]);
}

// ---------------- kernel 3: scatter, half-warp per edge, uint4 loads ---------
__global__ __launch_bounds__(256)
void scatter_kernel(const int* __restrict__ ei,
                    float* __restrict__ out, int E, int Etot) {
    const int lane = threadIdx.x & 31;
    const int warp = threadIdx.x >> 5;
    const int hl   = lane & 15;                     // lane within half-warp
    const int e    = blockIdx.x * 16 + warp * 2 + (lane >> 4);
    const bool valid = (e < Etot);
    const int  ec  = valid ? e : 0;

    int src, dst;
    if (ec < E) { src = ei[ec]; dst = ei[E + ec]; }
    else        { src = ec - E; dst = src; }

    // lanes 0..4 of each half-warp: weight = exp * rdenom (1/H folded)
    float wv = 0.f;
    if (hl < Hh)
        wv = g_w[(size_t)hl * Etot + ec] * g_rdenom[dst * Hh + hl];
    float w0 = __shfl_sync(0xffffffffu, wv, 0, 16);
    float w1 = __shfl_sync(0xffffffffu, wv, 1, 16);
    float w2 = __shfl_sync(0xffffffffu, wv, 2, 16);
    float w3 = __shfl_sync(0xffffffffu, wv, 3, 16);
    float w4 = __shfl_sync(0xffffffffu, wv, 4, 16);

    // each lane: 8 channels via one uint4 per head (head row = 16 uint4)
    const uint4* hp = (const uint4*)(g_h + (size_t)src * HC) + hl;
    uint4 u0 = hp[0 * 16];
    uint4 u1 = hp[1 * 16];
    uint4 u2 = hp[2 * 16];
    uint4 u3 = hp[3 * 16];
    uint4 u4 = hp[4 * 16];

    float a[8] = {0.f, 0.f, 0.f, 0.f, 0.f, 0.f, 0.f, 0.f};
    acc_head8(a, u0, w0);
    acc_head8(a, u1, w1);
    acc_head8(a, u2, w2);
    acc_head8(a, u3, w3);
    acc_head8(a, u4, w4);

    if (valid) {
        float* op = out + (size_t)dst * Cn + hl * 8;
        asm volatile("red.global.add.v4.f32 [%0], {%1, %2, %3, %4};"
                     :: "l"(op), "f"(a[0]), "f"(a[1]), "f"(a[2]), "f"(a[3])
                     : "memory");
        asm volatile("red.global.add.v4.f32 [%0], {%1, %2, %3, %4};"
                     :: "l"(op + 4), "f"(a[4]), "f"(a[5]), "f"(a[6]), "f"(a[7])
                     : "memory");
    }
}

// ---------------- launch ------------------------------------------------------
extern "C" void kernel_launch(void* const* d_in, const int* in_sizes, int n_in,
                              void* d_out, int out_size) {
    const float* features = (const float*)d_in[0];
    const float* W        = (const float*)d_in[1];
    const float* att_src  = (const float*)d_in[2];
    const float* att_dst  = (const float*)d_in[3];
    const float* bias     = (const float*)d_in[4];
    const int*   ei       = (const int*)d_in[5];   // int32 (jax x64 disabled)
    float*       out      = (float*)d_out;

    const int Nn   = in_sizes[0] / Cn;   // 20000
    const int E    = in_sizes[5] / 2;    // 320000
    const int Etot = E + Nn;             // 340000

    // 0) out = features + bias; zero denom
    {
        int work = Nn * Cn;
        init_kernel<<<(work + 255) / 256, 256>>>(features, bias, out, Nn);
    }

    // 1) h = features @ W via tf32 tensor cores, fused logits + fp16 store
    {
        dim3 grid(Hh, (Nn + TBM - 1) / TBM);   // (5, 157)
        gemm_tc_kernel<<<grid, 256>>>(features, W, att_src, att_dst, Nn);
    }

    // 2) exp + softmax denominators (stash exp planar in g_w)
    denom_kernel<<<(Etot + 255) / 256, 256>>>(ei, E, Etot);

    // 2.5) reciprocal denominators
    {
        int n = Nn * Hh;
        rdenom_kernel<<<(n + 255) / 256, 256>>>(n);
    }

    // 3) scatter: 16 edges per 256-thread block (half-warp per edge)
    scatter_kernel<<<(Etot + 15) / 16, 256>>>(ei, out, E, Etot);
}